// round 1
// baseline (speedup 1.0000x reference)
#include <cuda_runtime.h>
#include <cuda_bf16.h>
#include <cstdint>

// Problem dims
#define NUM_NODES 1000000
#define HIDDEN    128
#define OUT_DIM   64
#define FANOUT    16
#define N_SRC0    1048576
#define N_DST0    65536
#define N_DST1    4096

// ---------------- scratch (static device globals; no allocations) ----------
__device__ float g_X0[(size_t)N_DST0 * 256];   // [self(128) | neigh-mean(128)] per dst0 row, 64 MB
__device__ float g_H1[(size_t)N_DST0 * 128];   // layer-0 output (post-ReLU), 32 MB
__device__ float g_X1[(size_t)N_DST1 * 256];   // [self | mean] per dst1 row, 4 MB
__device__ float g_W0T[256 * 128];             // [k][n] = cat(W_self0, W_neigh0)^T
__device__ float g_b0[128];                    // b_self0 + b_neigh0
__device__ float g_WfT[256 * 64];              // [k][n] = (W_out @ cat(W_self1,W_neigh1))^T
__device__ float g_bf[64];                     // W_out @ (b_self1+b_neigh1) + b_out

// ---------------- prep: pack layer-0 weights -------------------------------
__global__ void prep_w0(const float* __restrict__ Ws0, const float* __restrict__ bs0,
                        const float* __restrict__ Wn0, const float* __restrict__ bn0) {
    int idx = blockIdx.x * blockDim.x + threadIdx.x;   // 32768 total
    if (idx < 256 * 128) {
        int k = idx >> 7;       // 0..255
        int n = idx & 127;      // 0..127
        g_W0T[idx] = (k < 128) ? Ws0[n * 128 + k] : Wn0[n * 128 + (k - 128)];
    }
    if (idx < 128) g_b0[idx] = bs0[idx] + bn0[idx];
}

// ---------------- prep: fuse layer-1 + output projection -------------------
// Wf[n][k] = sum_r W_out[n][r] * Wcat1[r][k];  store transposed g_WfT[k][n].
__global__ void prep_wf(const float* __restrict__ Ws1, const float* __restrict__ bs1,
                        const float* __restrict__ Wn1, const float* __restrict__ bn1,
                        const float* __restrict__ Wout, const float* __restrict__ bout) {
    int idx = blockIdx.x * blockDim.x + threadIdx.x;   // 16384 total
    if (idx < 256 * 64) {
        int k = idx >> 6;       // 0..255
        int n = idx & 63;       // 0..63
        float acc = 0.f;
        if (k < 128) {
            #pragma unroll 4
            for (int r = 0; r < 128; r++) acc += Wout[n * 128 + r] * Ws1[r * 128 + k];
        } else {
            int kk = k - 128;
            #pragma unroll 4
            for (int r = 0; r < 128; r++) acc += Wout[n * 128 + r] * Wn1[r * 128 + kk];
        }
        g_WfT[k * 64 + n] = acc;
    }
    if (idx < 64) {
        float acc = bout[idx];
        #pragma unroll 4
        for (int r = 0; r < 128; r++) acc += Wout[idx * 128 + r] * (bs1[r] + bn1[r]);
        g_bf[idx] = acc;
    }
}

// ---------------- layer-0 gather: build X0 [N_DST0, 256] -------------------
// One warp per dst row. Composes input_nodes[nbr_idx0[...]] so the 1M-row
// intermediate is never materialized.
__global__ __launch_bounds__(256) void gather0_kernel(
    const float* __restrict__ emb, const int* __restrict__ input_nodes,
    const int* __restrict__ nbr0) {
    int warp = (blockIdx.x * blockDim.x + threadIdx.x) >> 5;
    int lane = threadIdx.x & 31;
    if (warp >= N_DST0) return;

    int nj = 0;
    if (lane < FANOUT) nj = input_nodes[nbr0[warp * FANOUT + lane]];
    int self = input_nodes[warp];

    const float4* E = (const float4*)emb;                 // row stride = 32 float4
    float4 s = E[(size_t)self * 32 + lane];
    float ax = 0.f, ay = 0.f, az = 0.f, aw = 0.f;
    #pragma unroll
    for (int j = 0; j < FANOUT; j++) {
        int g = __shfl_sync(0xffffffffu, nj, j);
        float4 v = E[(size_t)g * 32 + lane];
        ax += v.x; ay += v.y; az += v.z; aw += v.w;
    }
    const float inv = 1.0f / (float)FANOUT;
    float4* X = (float4*)g_X0;                            // row stride = 64 float4
    X[(size_t)warp * 64 + lane]      = s;
    X[(size_t)warp * 64 + 32 + lane] = make_float4(ax * inv, ay * inv, az * inv, aw * inv);
}

// ---------------- layer-1 gather: build X1 [N_DST1, 256] from g_H1 ---------
__global__ __launch_bounds__(256) void gather1_kernel(const int* __restrict__ nbr1) {
    int warp = (blockIdx.x * blockDim.x + threadIdx.x) >> 5;
    int lane = threadIdx.x & 31;
    if (warp >= N_DST1) return;

    int nj = 0;
    if (lane < FANOUT) nj = nbr1[warp * FANOUT + lane];

    const float4* H = (const float4*)g_H1;                // row stride = 32 float4
    float4 s = H[(size_t)warp * 32 + lane];
    float ax = 0.f, ay = 0.f, az = 0.f, aw = 0.f;
    #pragma unroll
    for (int j = 0; j < FANOUT; j++) {
        int g = __shfl_sync(0xffffffffu, nj, j);
        float4 v = H[(size_t)g * 32 + lane];
        ax += v.x; ay += v.y; az += v.z; aw += v.w;
    }
    const float inv = 1.0f / (float)FANOUT;
    float4* X = (float4*)g_X1;
    X[(size_t)warp * 64 + lane]      = s;
    X[(size_t)warp * 64 + 32 + lane] = make_float4(ax * inv, ay * inv, az * inv, aw * inv);
}

// ---------------- gemm0: g_H1 = relu(g_X0 @ g_W0T + g_b0) ------------------
// M=65536, N=128, K=256. 128x128 tile, BK=16, 256 threads, 8x8 per thread.
__global__ __launch_bounds__(256) void gemm0_kernel() {
    const float* __restrict__ A = g_X0;      // [M,256]
    const float* __restrict__ B = g_W0T;     // [256,128]
    __shared__ float As[16][132];            // [k][row], pad (132 % 4 == 0)
    __shared__ float Bs[16][132];            // [k][n]

    int tid = threadIdx.x;
    int tx = tid & 15;         // n-tile coord
    int ty = tid >> 4;         // m-tile coord
    size_t block_row = (size_t)blockIdx.x * 128;
    const float* Ab = A + block_row * 256;

    float acc[8][8];
    #pragma unroll
    for (int i = 0; i < 8; i++)
        #pragma unroll
        for (int j = 0; j < 8; j++) acc[i][j] = 0.f;

    for (int k0 = 0; k0 < 256; k0 += 16) {
        // load A tile: 128 rows x 16 k = 512 float4
        #pragma unroll
        for (int it = 0; it < 2; it++) {
            int idx = it * 256 + tid;        // 0..511
            int row = idx >> 2;
            int c4  = idx & 3;
            float4 v = *(const float4*)(Ab + (size_t)row * 256 + k0 + c4 * 4);
            As[c4 * 4 + 0][row] = v.x;
            As[c4 * 4 + 1][row] = v.y;
            As[c4 * 4 + 2][row] = v.z;
            As[c4 * 4 + 3][row] = v.w;
        }
        // load B tile: 16 k x 128 n = 512 float4 (coalesced)
        #pragma unroll
        for (int it = 0; it < 2; it++) {
            int idx = it * 256 + tid;
            int kk = idx >> 5;
            int n4 = idx & 31;
            float4 v = *(const float4*)(B + (size_t)(k0 + kk) * 128 + n4 * 4);
            *(float4*)&Bs[kk][n4 * 4] = v;
        }
        __syncthreads();

        #pragma unroll
        for (int kk = 0; kk < 16; kk++) {
            float4 ra0 = *(float4*)&As[kk][ty * 8];
            float4 ra1 = *(float4*)&As[kk][ty * 8 + 4];
            float4 rb0 = *(float4*)&Bs[kk][tx * 8];
            float4 rb1 = *(float4*)&Bs[kk][tx * 8 + 4];
            float ra[8] = {ra0.x, ra0.y, ra0.z, ra0.w, ra1.x, ra1.y, ra1.z, ra1.w};
            float rb[8] = {rb0.x, rb0.y, rb0.z, rb0.w, rb1.x, rb1.y, rb1.z, rb1.w};
            #pragma unroll
            for (int i = 0; i < 8; i++)
                #pragma unroll
                for (int j = 0; j < 8; j++) acc[i][j] = fmaf(ra[i], rb[j], acc[i][j]);
        }
        __syncthreads();
    }

    #pragma unroll
    for (int i = 0; i < 8; i++) {
        size_t row = block_row + ty * 8 + i;
        #pragma unroll
        for (int j = 0; j < 8; j++) {
            int n = tx * 8 + j;
            float v = acc[i][j] + g_b0[n];
            g_H1[row * 128 + n] = fmaxf(v, 0.f);
        }
    }
}

// ---------------- gemm1: out = g_X1 @ g_WfT + g_bf -------------------------
// M=4096, N=64, K=256. Tiny: shared-B chunks of 64 k, 4 rows per block.
__global__ __launch_bounds__(256) void gemm1_kernel(float* __restrict__ C) {
    __shared__ float Bs[64][65];
    int tid = threadIdx.x;
    int r = blockIdx.x * 4 + (tid >> 6);
    int n = tid & 63;
    float acc = g_bf[n];
    for (int k0 = 0; k0 < 256; k0 += 64) {
        for (int i = tid; i < 64 * 64; i += 256)
            Bs[i >> 6][i & 63] = g_WfT[(size_t)(k0 + (i >> 6)) * 64 + (i & 63)];
        __syncthreads();
        const float* Ar = g_X1 + (size_t)r * 256 + k0;
        #pragma unroll 16
        for (int k = 0; k < 64; k++) acc = fmaf(Ar[k], Bs[k][n], acc);
        __syncthreads();
    }
    C[(size_t)r * 64 + n] = acc;
}

// ---------------- launch ---------------------------------------------------
extern "C" void kernel_launch(void* const* d_in, const int* in_sizes, int n_in,
                              void* d_out, int out_size) {
    const float* emb     = (const float*)d_in[0];
    const float* Ws0     = (const float*)d_in[1];
    const float* bs0     = (const float*)d_in[2];
    const float* Wn0     = (const float*)d_in[3];
    const float* bn0     = (const float*)d_in[4];
    const float* Ws1     = (const float*)d_in[5];
    const float* bs1     = (const float*)d_in[6];
    const float* Wn1     = (const float*)d_in[7];
    const float* bn1     = (const float*)d_in[8];
    const float* Wout    = (const float*)d_in[9];
    const float* bout    = (const float*)d_in[10];
    const int*   in_nodes = (const int*)d_in[11];
    const int*   nbr0    = (const int*)d_in[12];
    const int*   nbr1    = (const int*)d_in[13];
    float* out = (float*)d_out;

    // weight prep (tiny)
    prep_w0<<<128, 256>>>(Ws0, bs0, Wn0, bn0);
    prep_wf<<<64, 256>>>(Ws1, bs1, Wn1, bn1, Wout, bout);

    // layer 0: gather (+mean) then fused GEMM+bias+ReLU
    gather0_kernel<<<(N_DST0 * 32) / 256, 256>>>(emb, in_nodes, nbr0);
    gemm0_kernel<<<N_DST0 / 128, 256>>>();

    // layer 1 gather, then fused (layer1 + output-projection) GEMM
    gather1_kernel<<<(N_DST1 * 32) / 256, 256>>>(nbr1);
    gemm1_kernel<<<N_DST1 / 4, 256>>>(out);
}

// round 2
// speedup vs baseline: 1.4617x; 1.4617x over previous
#include <cuda_runtime.h>
#include <cuda_bf16.h>
#include <cstdint>

// Problem dims
#define NUM_NODES 1000000
#define HIDDEN    128
#define OUT_DIM   64
#define FANOUT    16
#define N_SRC0    1048576
#define N_DST0    65536
#define N_DST1    4096

// ---------------- scratch (static device globals; no allocations) ----------
__device__ float g_X0[(size_t)N_DST0 * 256];   // [self(128) | neigh-mean(128)] per dst0 row
__device__ float g_H1[(size_t)N_DST0 * 128];   // layer-0 output (post-ReLU)
__device__ float g_X1[(size_t)N_DST1 * 256];   // [self | mean] per dst1 row
__device__ float g_W0T[256 * 128];             // [k][n] = cat(W_self0, W_neigh0)^T
__device__ float g_b0[128];                    // b_self0 + b_neigh0
__device__ float g_WfT[256 * 64];              // [k][n] = (W_out @ cat(W_self1,W_neigh1))^T
__device__ float g_bf[64];                     // W_out @ (b_self1+b_neigh1) + b_out

// ---------------- helpers --------------------------------------------------
__device__ __forceinline__ uint32_t f2tf32(float f) {
    uint32_t r; asm("cvt.rna.tf32.f32 %0, %1;" : "=r"(r) : "f"(f)); return r;
}

__device__ __forceinline__ void mma_tf32(float c[4],
                                         uint32_t a0, uint32_t a1, uint32_t a2, uint32_t a3,
                                         uint32_t b0, uint32_t b1) {
    asm volatile(
        "mma.sync.aligned.m16n8k8.row.col.f32.tf32.tf32.f32 "
        "{%0,%1,%2,%3}, {%4,%5,%6,%7}, {%8,%9}, {%0,%1,%2,%3};"
        : "+f"(c[0]), "+f"(c[1]), "+f"(c[2]), "+f"(c[3])
        : "r"(a0), "r"(a1), "r"(a2), "r"(a3), "r"(b0), "r"(b1));
}

// ---------------- prep: pack layer-0 weights -------------------------------
__global__ void prep_w0(const float* __restrict__ Ws0, const float* __restrict__ bs0,
                        const float* __restrict__ Wn0, const float* __restrict__ bn0) {
    int idx = blockIdx.x * blockDim.x + threadIdx.x;   // 32768 total
    if (idx < 256 * 128) {
        int k = idx >> 7;       // 0..255
        int n = idx & 127;      // 0..127
        g_W0T[idx] = (k < 128) ? Ws0[n * 128 + k] : Wn0[n * 128 + (k - 128)];
    }
    if (idx < 128) g_b0[idx] = bs0[idx] + bn0[idx];
}

// ---------------- prep: fuse layer-1 + output projection -------------------
__global__ void prep_wf(const float* __restrict__ Ws1, const float* __restrict__ bs1,
                        const float* __restrict__ Wn1, const float* __restrict__ bn1,
                        const float* __restrict__ Wout, const float* __restrict__ bout) {
    int idx = blockIdx.x * blockDim.x + threadIdx.x;   // 16384 total
    if (idx < 256 * 64) {
        int k = idx >> 6;       // 0..255
        int n = idx & 63;       // 0..63
        float acc = 0.f;
        if (k < 128) {
            #pragma unroll 4
            for (int r = 0; r < 128; r++) acc += Wout[n * 128 + r] * Ws1[r * 128 + k];
        } else {
            int kk = k - 128;
            #pragma unroll 4
            for (int r = 0; r < 128; r++) acc += Wout[n * 128 + r] * Wn1[r * 128 + kk];
        }
        g_WfT[k * 64 + n] = acc;
    }
    if (idx < 64) {
        float acc = bout[idx];
        #pragma unroll 4
        for (int r = 0; r < 128; r++) acc += Wout[idx * 128 + r] * (bs1[r] + bn1[r]);
        g_bf[idx] = acc;
    }
}

// ---------------- layer-0 gather: build X0 [N_DST0, 256] -------------------
__global__ __launch_bounds__(256) void gather0_kernel(
    const float* __restrict__ emb, const int* __restrict__ input_nodes,
    const int* __restrict__ nbr0) {
    int warp = (blockIdx.x * blockDim.x + threadIdx.x) >> 5;
    int lane = threadIdx.x & 31;
    if (warp >= N_DST0) return;

    int nj = 0;
    if (lane < FANOUT) nj = input_nodes[nbr0[warp * FANOUT + lane]];
    int self = input_nodes[warp];

    const float4* E = (const float4*)emb;                 // row stride = 32 float4
    float4 s = E[(size_t)self * 32 + lane];
    float ax = 0.f, ay = 0.f, az = 0.f, aw = 0.f;
    #pragma unroll
    for (int j = 0; j < FANOUT; j++) {
        int g = __shfl_sync(0xffffffffu, nj, j);
        float4 v = E[(size_t)g * 32 + lane];
        ax += v.x; ay += v.y; az += v.z; aw += v.w;
    }
    const float inv = 1.0f / (float)FANOUT;
    float4* X = (float4*)g_X0;                            // row stride = 64 float4
    X[(size_t)warp * 64 + lane]      = s;
    X[(size_t)warp * 64 + 32 + lane] = make_float4(ax * inv, ay * inv, az * inv, aw * inv);
}

// ---------------- layer-1 gather: build X1 [N_DST1, 256] from g_H1 ---------
__global__ __launch_bounds__(256) void gather1_kernel(const int* __restrict__ nbr1) {
    int warp = (blockIdx.x * blockDim.x + threadIdx.x) >> 5;
    int lane = threadIdx.x & 31;
    if (warp >= N_DST1) return;

    int nj = 0;
    if (lane < FANOUT) nj = nbr1[warp * FANOUT + lane];

    const float4* H = (const float4*)g_H1;                // row stride = 32 float4
    float4 s = H[(size_t)warp * 32 + lane];
    float ax = 0.f, ay = 0.f, az = 0.f, aw = 0.f;
    #pragma unroll
    for (int j = 0; j < FANOUT; j++) {
        int g = __shfl_sync(0xffffffffu, nj, j);
        float4 v = H[(size_t)g * 32 + lane];
        ax += v.x; ay += v.y; az += v.z; aw += v.w;
    }
    const float inv = 1.0f / (float)FANOUT;
    float4* X = (float4*)g_X1;
    X[(size_t)warp * 64 + lane]      = s;
    X[(size_t)warp * 64 + 32 + lane] = make_float4(ax * inv, ay * inv, az * inv, aw * inv);
}

// ---------------- gemm0 (tensor cores, tf32) -------------------------------
// g_H1 = relu(g_X0 @ g_W0T + g_b0).  M=65536, N=128, K=256.
// CTA tile 128x128, BK=32, 8 warps in 2(m) x 4(n) grid, warp tile 64x32.
// mma.sync.m16n8k8 tf32. Conflict-free smem: As padded to 36 words/row
// (bank = 4r+c over the 8x4 quad pattern -> all 32 lanes distinct),
// Bs at 132 words/row (distinct banks likewise).
__global__ __launch_bounds__(256) void gemm0_tc_kernel() {
    __shared__ uint32_t As[128][36];   // [m][k]  (tf32 bits)
    __shared__ uint32_t Bs[32][132];   // [k][n]  (tf32 bits)

    const int tid  = threadIdx.x;
    const int l    = tid & 31;
    const int lm   = l >> 2;           // 0..7
    const int lk   = l & 3;            // 0..3
    const int wid  = tid >> 5;         // 0..7
    const int wm   = wid >> 2;         // 0..1
    const int wn   = wid & 3;          // 0..3
    const size_t block_row = (size_t)blockIdx.x * 128;
    const float* __restrict__ A = g_X0 + block_row * 256;
    const float* __restrict__ B = g_W0T;

    float acc[4][4][4];
    #pragma unroll
    for (int i = 0; i < 4; i++)
        #pragma unroll
        for (int j = 0; j < 4; j++)
            #pragma unroll
            for (int c = 0; c < 4; c++) acc[i][j][c] = 0.f;

    for (int k0 = 0; k0 < 256; k0 += 32) {
        // load A tile: 128 rows x 32 k = 1024 float4
        #pragma unroll
        for (int it = 0; it < 4; it++) {
            int idx = it * 256 + tid;          // 0..1023
            int row = idx >> 3;
            int c4  = idx & 7;
            float4 v = *(const float4*)(A + (size_t)row * 256 + k0 + c4 * 4);
            As[row][c4 * 4 + 0] = f2tf32(v.x);
            As[row][c4 * 4 + 1] = f2tf32(v.y);
            As[row][c4 * 4 + 2] = f2tf32(v.z);
            As[row][c4 * 4 + 3] = f2tf32(v.w);
        }
        // load B tile: 32 k x 128 n = 1024 float4 (coalesced, vector smem store)
        #pragma unroll
        for (int it = 0; it < 4; it++) {
            int idx = it * 256 + tid;
            int kk = idx >> 5;
            int n4 = idx & 31;
            float4 v = *(const float4*)(B + (size_t)(k0 + kk) * 128 + n4 * 4);
            uint4 t;
            t.x = f2tf32(v.x); t.y = f2tf32(v.y); t.z = f2tf32(v.z); t.w = f2tf32(v.w);
            *(uint4*)&Bs[kk][n4 * 4] = t;
        }
        __syncthreads();

        #pragma unroll
        for (int kk = 0; kk < 4; kk++) {
            const int k8 = kk * 8;
            uint32_t af[4][4], bf[4][2];
            #pragma unroll
            for (int mt = 0; mt < 4; mt++) {
                int mrow = wm * 64 + mt * 16 + lm;
                af[mt][0] = As[mrow    ][k8 + lk];
                af[mt][1] = As[mrow + 8][k8 + lk];
                af[mt][2] = As[mrow    ][k8 + lk + 4];
                af[mt][3] = As[mrow + 8][k8 + lk + 4];
            }
            #pragma unroll
            for (int nt = 0; nt < 4; nt++) {
                int ncol = wn * 32 + nt * 8 + lm;
                bf[nt][0] = Bs[k8 + lk    ][ncol];
                bf[nt][1] = Bs[k8 + lk + 4][ncol];
            }
            #pragma unroll
            for (int mt = 0; mt < 4; mt++)
                #pragma unroll
                for (int nt = 0; nt < 4; nt++)
                    mma_tf32(acc[mt][nt], af[mt][0], af[mt][1], af[mt][2], af[mt][3],
                             bf[nt][0], bf[nt][1]);
        }
        __syncthreads();
    }

    // epilogue: bias + relu, float2 stores
    float2* __restrict__ H2 = (float2*)g_H1;      // row stride = 64 float2
    #pragma unroll
    for (int nt = 0; nt < 4; nt++) {
        int col = wn * 32 + nt * 8 + lk * 2;
        float bv0 = g_b0[col], bv1 = g_b0[col + 1];
        #pragma unroll
        for (int mt = 0; mt < 4; mt++) {
            size_t row0 = block_row + wm * 64 + mt * 16 + lm;
            float2 v0 = make_float2(fmaxf(acc[mt][nt][0] + bv0, 0.f),
                                    fmaxf(acc[mt][nt][1] + bv1, 0.f));
            float2 v1 = make_float2(fmaxf(acc[mt][nt][2] + bv0, 0.f),
                                    fmaxf(acc[mt][nt][3] + bv1, 0.f));
            H2[row0 * 64 + (col >> 1)]       = v0;
            H2[(row0 + 8) * 64 + (col >> 1)] = v1;
        }
    }
}

// ---------------- gemm1: out = g_X1 @ g_WfT + g_bf -------------------------
__global__ __launch_bounds__(256) void gemm1_kernel(float* __restrict__ C) {
    __shared__ float Bs[64][65];
    int tid = threadIdx.x;
    int r = blockIdx.x * 4 + (tid >> 6);
    int n = tid & 63;
    float acc = g_bf[n];
    for (int k0 = 0; k0 < 256; k0 += 64) {
        for (int i = tid; i < 64 * 64; i += 256)
            Bs[i >> 6][i & 63] = g_WfT[(size_t)(k0 + (i >> 6)) * 64 + (i & 63)];
        __syncthreads();
        const float* Ar = g_X1 + (size_t)r * 256 + k0;
        #pragma unroll 16
        for (int k = 0; k < 64; k++) acc = fmaf(Ar[k], Bs[k][n], acc);
        __syncthreads();
    }
    C[(size_t)r * 64 + n] = acc;
}

// ---------------- launch ---------------------------------------------------
extern "C" void kernel_launch(void* const* d_in, const int* in_sizes, int n_in,
                              void* d_out, int out_size) {
    const float* emb      = (const float*)d_in[0];
    const float* Ws0      = (const float*)d_in[1];
    const float* bs0      = (const float*)d_in[2];
    const float* Wn0      = (const float*)d_in[3];
    const float* bn0      = (const float*)d_in[4];
    const float* Ws1      = (const float*)d_in[5];
    const float* bs1      = (const float*)d_in[6];
    const float* Wn1      = (const float*)d_in[7];
    const float* bn1      = (const float*)d_in[8];
    const float* Wout     = (const float*)d_in[9];
    const float* bout     = (const float*)d_in[10];
    const int*   in_nodes = (const int*)d_in[11];
    const int*   nbr0     = (const int*)d_in[12];
    const int*   nbr1     = (const int*)d_in[13];
    float* out = (float*)d_out;

    // weight prep (tiny)
    prep_w0<<<128, 256>>>(Ws0, bs0, Wn0, bn0);
    prep_wf<<<64, 256>>>(Ws1, bs1, Wn1, bn1, Wout, bout);

    // layer 0: gather (+mean) then tensor-core GEMM+bias+ReLU
    gather0_kernel<<<(N_DST0 * 32) / 256, 256>>>(emb, in_nodes, nbr0);
    gemm0_tc_kernel<<<N_DST0 / 128, 256>>>();

    // layer 1 gather, then fused (layer1 + output-projection) GEMM
    gather1_kernel<<<(N_DST1 * 32) / 256, 256>>>(nbr1);
    gemm1_kernel<<<N_DST1 / 4, 256>>>(out);
}

// round 3
// speedup vs baseline: 1.5249x; 1.0432x over previous
#include <cuda_runtime.h>
#include <cuda_bf16.h>
#include <cstdint>

// Problem dims
#define NUM_NODES 1000000
#define HIDDEN    128
#define OUT_DIM   64
#define FANOUT    16
#define N_SRC0    1048576
#define N_DST0    65536
#define N_DST1    4096

#define TILE_M 64            // dst rows per CTA in fused layer-0 kernel

// ---------------- scratch (static device globals; no allocations) ----------
__device__ float g_H1[(size_t)N_DST0 * 128];   // layer-0 output (post-ReLU)
__device__ float g_X1[(size_t)N_DST1 * 256];   // [self | mean] per dst1 row
__device__ float g_W0T[256 * 128];             // [k][n] = cat(W_self0, W_neigh0)^T
__device__ float g_b0[128];                    // b_self0 + b_neigh0
__device__ float g_WfT[256 * 64];              // [k][n] = (W_out @ cat(W_self1,W_neigh1))^T
__device__ float g_bf[64];                     // W_out @ (b_self1+b_neigh1) + b_out

// ---------------- helpers --------------------------------------------------
__device__ __forceinline__ uint32_t f2tf32(float f) {
    uint32_t r; asm("cvt.rna.tf32.f32 %0, %1;" : "=r"(r) : "f"(f)); return r;
}

__device__ __forceinline__ void mma_tf32(float c[4],
                                         uint32_t a0, uint32_t a1, uint32_t a2, uint32_t a3,
                                         uint32_t b0, uint32_t b1) {
    asm volatile(
        "mma.sync.aligned.m16n8k8.row.col.f32.tf32.tf32.f32 "
        "{%0,%1,%2,%3}, {%4,%5,%6,%7}, {%8,%9}, {%0,%1,%2,%3};"
        : "+f"(c[0]), "+f"(c[1]), "+f"(c[2]), "+f"(c[3])
        : "r"(a0), "r"(a1), "r"(a2), "r"(a3), "r"(b0), "r"(b1));
}

// ---------------- prep: pack layer-0 weights -------------------------------
__global__ void prep_w0(const float* __restrict__ Ws0, const float* __restrict__ bs0,
                        const float* __restrict__ Wn0, const float* __restrict__ bn0) {
    int idx = blockIdx.x * blockDim.x + threadIdx.x;   // 32768 total
    if (idx < 256 * 128) {
        int k = idx >> 7;
        int n = idx & 127;
        g_W0T[idx] = (k < 128) ? Ws0[n * 128 + k] : Wn0[n * 128 + (k - 128)];
    }
    if (idx < 128) g_b0[idx] = bs0[idx] + bn0[idx];
}

// ---------------- prep: fuse layer-1 + output projection -------------------
__global__ void prep_wf(const float* __restrict__ Ws1, const float* __restrict__ bs1,
                        const float* __restrict__ Wn1, const float* __restrict__ bn1,
                        const float* __restrict__ Wout, const float* __restrict__ bout) {
    int idx = blockIdx.x * blockDim.x + threadIdx.x;   // 16384 total
    if (idx < 256 * 64) {
        int k = idx >> 6;
        int n = idx & 63;
        float acc = 0.f;
        if (k < 128) {
            #pragma unroll 4
            for (int r = 0; r < 128; r++) acc += Wout[n * 128 + r] * Ws1[r * 128 + k];
        } else {
            int kk = k - 128;
            #pragma unroll 4
            for (int r = 0; r < 128; r++) acc += Wout[n * 128 + r] * Wn1[r * 128 + kk];
        }
        g_WfT[k * 64 + n] = acc;
    }
    if (idx < 64) {
        float acc = bout[idx];
        #pragma unroll 4
        for (int r = 0; r < 128; r++) acc += Wout[idx * 128 + r] * (bs1[r] + bn1[r]);
        g_bf[idx] = acc;
    }
}

// ---------------- fused layer-0: gather + mean + tf32 GEMM + bias + ReLU ---
// Per CTA: 64 dst rows. Smem A tile [64][260] tf32, B slice [32][132] tf32,
// staged composed indices. 2 CTAs/SM so gather (DRAM) overlaps MMA (tensor).
#define AS_STRIDE 260
#define BS_STRIDE 132
#define SM_AS_WORDS (TILE_M * AS_STRIDE)               // 16640
#define SM_BS_WORDS (32 * BS_STRIDE)                   // 4224
#define SM_IDX_WORDS (TILE_M * FANOUT + TILE_M)        // 1088
#define SM_TOTAL_BYTES ((SM_AS_WORDS + SM_BS_WORDS + SM_IDX_WORDS) * 4)

__global__ __launch_bounds__(256, 2) void layer0_fused_kernel(
    const float* __restrict__ emb, const int* __restrict__ input_nodes,
    const int* __restrict__ nbr0) {
    extern __shared__ uint32_t smem[];
    uint32_t (*As)[AS_STRIDE] = (uint32_t (*)[AS_STRIDE])smem;
    uint32_t (*Bs)[BS_STRIDE] = (uint32_t (*)[BS_STRIDE])(smem + SM_AS_WORDS);
    int* s_idx  = (int*)(smem + SM_AS_WORDS + SM_BS_WORDS);          // [64*16]
    int* s_self = s_idx + TILE_M * FANOUT;                           // [64]

    const int tid  = threadIdx.x;
    const int lane = tid & 31;
    const int wid  = tid >> 5;
    const int dst0 = blockIdx.x * TILE_M;

    // ---- Phase A1: stage composed indices (deep MLP, coalesced) ----
    #pragma unroll
    for (int it = 0; it < (TILE_M * FANOUT) / 256; it++) {           // 4 iters
        int i = it * 256 + tid;
        s_idx[i] = input_nodes[nbr0[(size_t)dst0 * FANOUT + i]];
    }
    if (tid < TILE_M) s_self[tid] = input_nodes[dst0 + tid];
    __syncthreads();

    // ---- Phase A2: feature gather + mean -> tf32 smem A tile ----
    // Warp w handles rows w*8 .. w*8+7; 17 independent 512B row loads per row.
    const float4* E = (const float4*)emb;                            // row = 32 float4
    const float inv = 1.0f / (float)FANOUT;
    #pragma unroll
    for (int rr = 0; rr < 8; rr++) {
        int r = wid * 8 + rr;
        float4 s = E[(size_t)s_self[r] * 32 + lane];
        float ax = 0.f, ay = 0.f, az = 0.f, aw = 0.f;
        #pragma unroll
        for (int j = 0; j < FANOUT; j++) {
            int g = s_idx[r * FANOUT + j];
            float4 v = E[(size_t)g * 32 + lane];
            ax += v.x; ay += v.y; az += v.z; aw += v.w;
        }
        uint4 ts; ts.x = f2tf32(s.x); ts.y = f2tf32(s.y); ts.z = f2tf32(s.z); ts.w = f2tf32(s.w);
        *(uint4*)&As[r][lane * 4] = ts;
        uint4 tn; tn.x = f2tf32(ax * inv); tn.y = f2tf32(ay * inv);
        tn.z = f2tf32(az * inv); tn.w = f2tf32(aw * inv);
        *(uint4*)&As[r][128 + lane * 4] = tn;
    }
    __syncthreads();

    // ---- Phase B: GEMM 64x128x256 (tf32 m16n8k8), warps 2(m) x 4(n) ----
    const int lm = lane >> 2;          // 0..7
    const int lk = lane & 3;           // 0..3
    const int wm = wid >> 2;           // 0..1
    const int wn = wid & 3;            // 0..3
    const float* __restrict__ B = g_W0T;

    float acc[2][4][4];
    #pragma unroll
    for (int i = 0; i < 2; i++)
        #pragma unroll
        for (int j = 0; j < 4; j++)
            #pragma unroll
            for (int c = 0; c < 4; c++) acc[i][j][c] = 0.f;

    for (int k0 = 0; k0 < 256; k0 += 32) {
        // load B slice: 32 k x 128 n = 1024 float4 (L2-hot)
        #pragma unroll
        for (int it = 0; it < 4; it++) {
            int idx = it * 256 + tid;
            int kk = idx >> 5;
            int n4 = idx & 31;
            float4 v = *(const float4*)(B + (size_t)(k0 + kk) * 128 + n4 * 4);
            uint4 t;
            t.x = f2tf32(v.x); t.y = f2tf32(v.y); t.z = f2tf32(v.z); t.w = f2tf32(v.w);
            *(uint4*)&Bs[kk][n4 * 4] = t;
        }
        __syncthreads();

        #pragma unroll
        for (int kk = 0; kk < 4; kk++) {
            const int k8 = kk * 8;
            uint32_t af[2][4], bf[4][2];
            #pragma unroll
            for (int mt = 0; mt < 2; mt++) {
                int mrow = wm * 32 + mt * 16 + lm;
                af[mt][0] = As[mrow    ][k0 + k8 + lk];
                af[mt][1] = As[mrow + 8][k0 + k8 + lk];
                af[mt][2] = As[mrow    ][k0 + k8 + lk + 4];
                af[mt][3] = As[mrow + 8][k0 + k8 + lk + 4];
            }
            #pragma unroll
            for (int nt = 0; nt < 4; nt++) {
                int ncol = wn * 32 + nt * 8 + lm;
                bf[nt][0] = Bs[k8 + lk    ][ncol];
                bf[nt][1] = Bs[k8 + lk + 4][ncol];
            }
            #pragma unroll
            for (int mt = 0; mt < 2; mt++)
                #pragma unroll
                for (int nt = 0; nt < 4; nt++)
                    mma_tf32(acc[mt][nt], af[mt][0], af[mt][1], af[mt][2], af[mt][3],
                             bf[nt][0], bf[nt][1]);
        }
        __syncthreads();
    }

    // ---- epilogue: bias + relu -> g_H1 ----
    float2* __restrict__ H2 = (float2*)g_H1;      // row stride = 64 float2
    #pragma unroll
    for (int nt = 0; nt < 4; nt++) {
        int col = wn * 32 + nt * 8 + lk * 2;
        float bv0 = g_b0[col], bv1 = g_b0[col + 1];
        #pragma unroll
        for (int mt = 0; mt < 2; mt++) {
            size_t row0 = (size_t)dst0 + wm * 32 + mt * 16 + lm;
            float2 v0 = make_float2(fmaxf(acc[mt][nt][0] + bv0, 0.f),
                                    fmaxf(acc[mt][nt][1] + bv1, 0.f));
            float2 v1 = make_float2(fmaxf(acc[mt][nt][2] + bv0, 0.f),
                                    fmaxf(acc[mt][nt][3] + bv1, 0.f));
            H2[row0 * 64 + (col >> 1)]       = v0;
            H2[(row0 + 8) * 64 + (col >> 1)] = v1;
        }
    }
}

// ---------------- layer-1 gather: build X1 [N_DST1, 256] from g_H1 ---------
__global__ __launch_bounds__(256) void gather1_kernel(const int* __restrict__ nbr1) {
    int warp = (blockIdx.x * blockDim.x + threadIdx.x) >> 5;
    int lane = threadIdx.x & 31;
    if (warp >= N_DST1) return;

    int nj = 0;
    if (lane < FANOUT) nj = nbr1[warp * FANOUT + lane];

    const float4* H = (const float4*)g_H1;                // row stride = 32 float4
    float4 s = H[(size_t)warp * 32 + lane];
    float ax = 0.f, ay = 0.f, az = 0.f, aw = 0.f;
    #pragma unroll
    for (int j = 0; j < FANOUT; j++) {
        int g = __shfl_sync(0xffffffffu, nj, j);
        float4 v = H[(size_t)g * 32 + lane];
        ax += v.x; ay += v.y; az += v.z; aw += v.w;
    }
    const float inv = 1.0f / (float)FANOUT;
    float4* X = (float4*)g_X1;
    X[(size_t)warp * 64 + lane]      = s;
    X[(size_t)warp * 64 + 32 + lane] = make_float4(ax * inv, ay * inv, az * inv, aw * inv);
}

// ---------------- gemm1: out = g_X1 @ g_WfT + g_bf -------------------------
__global__ __launch_bounds__(256) void gemm1_kernel(float* __restrict__ C) {
    __shared__ float Bs[64][65];
    int tid = threadIdx.x;
    int r = blockIdx.x * 4 + (tid >> 6);
    int n = tid & 63;
    float acc = g_bf[n];
    for (int k0 = 0; k0 < 256; k0 += 64) {
        for (int i = tid; i < 64 * 64; i += 256)
            Bs[i >> 6][i & 63] = g_WfT[(size_t)(k0 + (i >> 6)) * 64 + (i & 63)];
        __syncthreads();
        const float* Ar = g_X1 + (size_t)r * 256 + k0;
        #pragma unroll 16
        for (int k = 0; k < 64; k++) acc = fmaf(Ar[k], Bs[k][n], acc);
        __syncthreads();
    }
    C[(size_t)r * 64 + n] = acc;
}

// ---------------- launch ---------------------------------------------------
extern "C" void kernel_launch(void* const* d_in, const int* in_sizes, int n_in,
                              void* d_out, int out_size) {
    const float* emb      = (const float*)d_in[0];
    const float* Ws0      = (const float*)d_in[1];
    const float* bs0      = (const float*)d_in[2];
    const float* Wn0      = (const float*)d_in[3];
    const float* bn0      = (const float*)d_in[4];
    const float* Ws1      = (const float*)d_in[5];
    const float* bs1      = (const float*)d_in[6];
    const float* Wn1      = (const float*)d_in[7];
    const float* bn1      = (const float*)d_in[8];
    const float* Wout     = (const float*)d_in[9];
    const float* bout     = (const float*)d_in[10];
    const int*   in_nodes = (const int*)d_in[11];
    const int*   nbr0     = (const int*)d_in[12];
    const int*   nbr1     = (const int*)d_in[13];
    float* out = (float*)d_out;

    cudaFuncSetAttribute(layer0_fused_kernel,
                         cudaFuncAttributeMaxDynamicSharedMemorySize, SM_TOTAL_BYTES);

    // weight prep (tiny)
    prep_w0<<<128, 256>>>(Ws0, bs0, Wn0, bn0);
    prep_wf<<<64, 256>>>(Ws1, bs1, Wn1, bn1, Wout, bout);

    // layer 0: fused gather + mean + GEMM + bias + ReLU
    layer0_fused_kernel<<<N_DST0 / TILE_M, 256, SM_TOTAL_BYTES>>>(emb, in_nodes, nbr0);

    // layer 1 gather, then fused (layer1 + output-projection) GEMM
    gather1_kernel<<<(N_DST1 * 32) / 256, 256>>>(nbr1);
    gemm1_kernel<<<N_DST1 / 4, 256>>>(out);
}